// round 1
// baseline (speedup 1.0000x reference)
#include <cuda_runtime.h>
#include <math.h>
#include <stdint.h>

#define LSEQ 1024
#define WDIM 300
#define PDIM 100
#define DIN0 400
#define HDIR 512
#define HID  1024
#define G4   2048      // 4*HDIR
#define NCD  64        // CTAs per direction in recurrence

// ---------------- scratch (static device globals; no runtime allocation) ----
__device__ float g_emb[LSEQ * DIN0];           // 1.6 MB
__device__ float g_xp[2ull * LSEQ * G4];       // 16 MB (reused across layers)
__device__ float g_h0[LSEQ * HID];             // 4 MB
__device__ float g_h1[LSEQ * HID];             // 4 MB
__device__ float g_feat[2ull * LSEQ * 512];    // 4 MB
__device__ float g_s[2 * LSEQ];
__device__ int   g_cnt[64];                    // [0]=fwd, [32]=bwd (pad to avoid false sharing)

__global__ void reset_cnt_kernel() { g_cnt[0] = 0; g_cnt[32] = 0; }

// ---------------- embedding gather --------------------------------------
__global__ void embed_kernel(const int* __restrict__ wt, const int* __restrict__ pt,
                             const float* __restrict__ wemb, const float* __restrict__ pemb) {
    int t = blockIdx.x;
    int w = wt[t], p = pt[t];
    for (int i = threadIdx.x; i < WDIM; i += blockDim.x)
        g_emb[t * DIN0 + i] = wemb[(size_t)w * WDIM + i];
    for (int i = threadIdx.x; i < PDIM; i += blockDim.x)
        g_emb[t * DIN0 + WDIM + i] = pemb[(size_t)p * PDIM + i];
}

// ---------------- C[M,N] = A[M,K] @ B[N,K]^T + bias[N] -------------------
// BM=BN=64, BK=16, 256 threads, 4x4 microtile. Requires M%64==0, N%64==0, K%16==0.
__global__ __launch_bounds__(256) void gemm_abt_bias(
    const float* __restrict__ A, const float* __restrict__ B,
    const float* __restrict__ bias, float* __restrict__ C,
    int M, int N, int K)
{
    __shared__ float As[16][64];
    __shared__ float Bs[16][64];
    int tid  = threadIdx.x;
    int m0   = blockIdx.y * 64, n0 = blockIdx.x * 64;
    int lrow = tid >> 2;
    int lc4  = (tid & 3) * 4;
    int tx   = tid & 15, ty = tid >> 4;

    float acc[4][4];
#pragma unroll
    for (int i = 0; i < 4; i++)
#pragma unroll
        for (int j = 0; j < 4; j++) acc[i][j] = 0.f;

    for (int k0 = 0; k0 < K; k0 += 16) {
        float4 a = *(const float4*)(A + (size_t)(m0 + lrow) * K + k0 + lc4);
        float4 b = *(const float4*)(B + (size_t)(n0 + lrow) * K + k0 + lc4);
        As[lc4 + 0][lrow] = a.x; As[lc4 + 1][lrow] = a.y;
        As[lc4 + 2][lrow] = a.z; As[lc4 + 3][lrow] = a.w;
        Bs[lc4 + 0][lrow] = b.x; Bs[lc4 + 1][lrow] = b.y;
        Bs[lc4 + 2][lrow] = b.z; Bs[lc4 + 3][lrow] = b.w;
        __syncthreads();
#pragma unroll
        for (int k = 0; k < 16; k++) {
            float ar[4], br[4];
#pragma unroll
            for (int i = 0; i < 4; i++) ar[i] = As[k][ty * 4 + i];
#pragma unroll
            for (int j = 0; j < 4; j++) br[j] = Bs[k][tx * 4 + j];
#pragma unroll
            for (int i = 0; i < 4; i++)
#pragma unroll
                for (int j = 0; j < 4; j++) acc[i][j] = fmaf(ar[i], br[j], acc[i][j]);
        }
        __syncthreads();
    }
#pragma unroll
    for (int i = 0; i < 4; i++) {
        int m = m0 + ty * 4 + i;
#pragma unroll
        for (int j = 0; j < 4; j++) {
            int n = n0 + tx * 4 + j;
            C[(size_t)m * N + n] = acc[i][j] + bias[n];
        }
    }
}

// ---------------- persistent bidirectional LSTM recurrence ----------------
// grid = 128 CTAs (64 per direction), 256 threads.
// CTA b of direction d owns h-outputs [b*8, b*8+8). Warp j handles output j:
// each lane holds the 4 gate-row weight slices (k = lane + 32*i, i<16) in REGISTERS.
// Step barrier: release-add / acquire-spin on g_cnt; h broadcast via hout rows in L2.
__device__ __forceinline__ float sigmoidf_(float x) { return 1.f / (1.f + expf(-x)); }

__global__ __launch_bounds__(256, 1) void lstm_rec(
    const float* __restrict__ Whh2,   // [2][2048][512]
    const float* __restrict__ xp2,    // [2][L][2048]
    float* hout)                      // [L][1024]
{
    int dir  = blockIdx.x >> 6;
    int b    = blockIdx.x & 63;
    int tid  = threadIdx.x;
    int j    = tid >> 5;      // warp -> local h index
    int lane = tid & 31;
    int hglob = b * 8 + j;
    int hcol  = dir * HDIR + hglob;
    int* cnt  = &g_cnt[dir * 32];

    const float* W  = Whh2 + (size_t)dir * G4 * HDIR;
    const float* xp = xp2  + (size_t)dir * LSEQ * G4;

    // load weights into registers (once)
    float w[4][16];
#pragma unroll
    for (int q = 0; q < 4; q++) {
        const float* wr = W + (size_t)(q * HDIR + hglob) * HDIR;
#pragma unroll
        for (int i = 0; i < 16; i++) w[q][i] = wr[lane + 32 * i];
    }

    __shared__ float sh[HDIR];
    float c = 0.f;

    for (int s = 0; s < LSEQ; ++s) {
        int t = dir ? (LSEQ - 1 - s) : s;

        if (s == 0) {
            for (int i = tid; i < HDIR; i += 256) sh[i] = 0.f;
        } else {
            if (tid == 0) {
                int target = s * NCD, v;
                do {
                    asm volatile("ld.acquire.gpu.global.s32 %0, [%1];"
                                 : "=r"(v) : "l"(cnt));
                } while (v < target);
            }
            __syncthreads();
            int tp = dir ? (t + 1) : (t - 1);
            const float* hp = hout + (size_t)tp * HID + dir * HDIR;
            for (int i = tid; i < HDIR; i += 256) sh[i] = __ldcg(hp + i);
        }
        __syncthreads();

        // prefetch xp values for this output's 4 gate rows (lanes 0..3)
        float xpv = 0.f;
        if (lane < 4) xpv = __ldg(xp + (size_t)t * G4 + lane * HDIR + hglob);

        float hreg[16];
#pragma unroll
        for (int i = 0; i < 16; i++) hreg[i] = sh[lane + 32 * i];

        float s0 = 0.f, s1 = 0.f, s2 = 0.f, s3 = 0.f;
#pragma unroll
        for (int i = 0; i < 16; i++) {
            s0 = fmaf(w[0][i], hreg[i], s0);
            s1 = fmaf(w[1][i], hreg[i], s1);
            s2 = fmaf(w[2][i], hreg[i], s2);
            s3 = fmaf(w[3][i], hreg[i], s3);
        }
#pragma unroll
        for (int off = 16; off; off >>= 1) {
            s0 += __shfl_xor_sync(0xffffffffu, s0, off);
            s1 += __shfl_xor_sync(0xffffffffu, s1, off);
            s2 += __shfl_xor_sync(0xffffffffu, s2, off);
            s3 += __shfl_xor_sync(0xffffffffu, s3, off);
        }
        float x0 = __shfl_sync(0xffffffffu, xpv, 0);
        float x1 = __shfl_sync(0xffffffffu, xpv, 1);
        float x2 = __shfl_sync(0xffffffffu, xpv, 2);
        float x3 = __shfl_sync(0xffffffffu, xpv, 3);

        if (lane == 0) {
            float gi = sigmoidf_(s0 + x0);
            float gf = sigmoidf_(s1 + x1);
            float gg = tanhf(s2 + x2);
            float go = sigmoidf_(s3 + x3);
            c = gf * c + gi * gg;
            hout[(size_t)t * HID + hcol] = go * tanhf(c);
        }
        __syncthreads();                 // all warps' h writes done before arrive
        if (tid == 0) {
            int one = 1;
            asm volatile("red.release.gpu.global.add.s32 [%0], %1;"
                         :: "l"(cnt), "r"(one) : "memory");
        }
    }
}

// ---------------- score epilogue ------------------------------------------
__global__ void score_reduce(const float* __restrict__ wo) {
    int t = blockIdx.x, tid = threadIdx.x;
    float a0 = 0.f, a1 = 0.f;
    for (int jj = tid; jj < 512; jj += 256) {
        a0 += wo[jj]       * tanhf(g_feat[(size_t)t * 512 + jj]);
        a1 += wo[512 + jj] * tanhf(g_feat[(size_t)LSEQ * 512 + (size_t)t * 512 + jj]);
    }
#pragma unroll
    for (int off = 16; off; off >>= 1) {
        a0 += __shfl_xor_sync(0xffffffffu, a0, off);
        a1 += __shfl_xor_sync(0xffffffffu, a1, off);
    }
    __shared__ float r0[8], r1[8];
    if ((tid & 31) == 0) { r0[tid >> 5] = a0; r1[tid >> 5] = a1; }
    __syncthreads();
    if (tid == 0) {
        float t0 = 0.f, t1 = 0.f;
#pragma unroll
        for (int i = 0; i < 8; i++) { t0 += r0[i]; t1 += r1[i]; }
        g_s[t] = t0;           // s_head
        g_s[LSEQ + t] = t1;    // s_modif
    }
}

__global__ void score_out(float* __restrict__ out, const float* __restrict__ bo) {
    int m = blockIdx.x;
    float base = g_s[LSEQ + m] + bo[0];
    for (int h = threadIdx.x; h < LSEQ; h += blockDim.x)
        out[(size_t)m * LSEQ + h] = base + g_s[h];
}

// ---------------- launch ---------------------------------------------------
extern "C" void kernel_launch(void* const* d_in, const int* in_sizes, int n_in,
                              void* d_out, int out_size) {
    const int*   wt   = (const int*)d_in[0];
    const int*   pt   = (const int*)d_in[1];
    const float* wemb = (const float*)d_in[2];
    const float* pemb = (const float*)d_in[3];
    const float* Wih0 = (const float*)d_in[4];
    const float* Whh0 = (const float*)d_in[5];
    const float* b0   = (const float*)d_in[6];
    const float* Wih1 = (const float*)d_in[7];
    const float* Whh1 = (const float*)d_in[8];
    const float* b1   = (const float*)d_in[9];
    const float* Wh   = (const float*)d_in[10];
    const float* bh   = (const float*)d_in[11];
    const float* Wm   = (const float*)d_in[12];
    const float* bm   = (const float*)d_in[13];
    const float* wo   = (const float*)d_in[14];
    const float* bo   = (const float*)d_in[15];
    float* out = (float*)d_out;

    float *p_emb, *p_xp, *p_h0, *p_h1, *p_feat;
    cudaGetSymbolAddress((void**)&p_emb,  g_emb);
    cudaGetSymbolAddress((void**)&p_xp,   g_xp);
    cudaGetSymbolAddress((void**)&p_h0,   g_h0);
    cudaGetSymbolAddress((void**)&p_h1,   g_h1);
    cudaGetSymbolAddress((void**)&p_feat, g_feat);

    embed_kernel<<<LSEQ, 128>>>(wt, pt, wemb, pemb);

    // layer 0 input projections: [L,400] @ [2048,400]^T
    gemm_abt_bias<<<dim3(G4 / 64, LSEQ / 64), 256>>>(p_emb, Wih0, b0, p_xp, LSEQ, G4, DIN0);
    gemm_abt_bias<<<dim3(G4 / 64, LSEQ / 64), 256>>>(p_emb, Wih0 + (size_t)G4 * DIN0, b0 + G4,
                                                     p_xp + (size_t)LSEQ * G4, LSEQ, G4, DIN0);
    reset_cnt_kernel<<<1, 1>>>();
    lstm_rec<<<128, 256>>>(Whh0, p_xp, p_h0);

    // layer 1 input projections: [L,1024] @ [2048,1024]^T
    gemm_abt_bias<<<dim3(G4 / 64, LSEQ / 64), 256>>>(p_h0, Wih1, b1, p_xp, LSEQ, G4, HID);
    gemm_abt_bias<<<dim3(G4 / 64, LSEQ / 64), 256>>>(p_h0, Wih1 + (size_t)G4 * HID, b1 + G4,
                                                     p_xp + (size_t)LSEQ * G4, LSEQ, G4, HID);
    reset_cnt_kernel<<<1, 1>>>();
    lstm_rec<<<128, 256>>>(Whh1, p_xp, p_h1);

    // head/modifier features: [L,1024] @ [512,1024]^T
    gemm_abt_bias<<<dim3(512 / 64, LSEQ / 64), 256>>>(p_h1, Wh, bh, p_feat, LSEQ, 512, HID);
    gemm_abt_bias<<<dim3(512 / 64, LSEQ / 64), 256>>>(p_h1, Wm, bm,
                                                      p_feat + (size_t)LSEQ * 512, LSEQ, 512, HID);

    score_reduce<<<LSEQ, 256>>>(wo);
    score_out<<<LSEQ, 256>>>(out, bo);
}